// round 15
// baseline (speedup 1.0000x reference)
#include <cuda_runtime.h>
#include <cuda_fp16.h>
#include <stdint.h>

#define SS 512
#define BB 256
#define VOC 32000
#define HID 256
#define G4 1024
#define NCLS 8

__device__ float g_eW[(size_t)2 * VOC * G4];                 // [d][v][p], bias baked
__device__ __align__(16) __half g_eh[VOC * 128], g_el[VOC * 128];
__device__ __align__(16) uint32_t g_WiFh[131072], g_WiFl[131072];
__device__ __align__(16) uint32_t g_WhFh[524288];
__device__ __align__(16) __half g_hh[2 * 2 * BB * HID];      // ping-pong h (fp16)
__device__ float g_c[2 * BB * HID];
__device__ unsigned g_bar[16];

__device__ __forceinline__ uint32_t smem_u32(const void* p) {
    uint32_t a;
    asm("{ .reg .u64 t; cvta.to.shared.u64 t, %1; cvt.u32.u64 %0, t; }" : "=r"(a) : "l"(p));
    return a;
}
#define CP16(dst, src) asm volatile("cp.async.cg.shared.global [%0], [%1], 16;" :: "r"(dst), "l"(src))
#define CPCOMMIT() asm volatile("cp.async.commit_group;" ::: "memory")
#define CPWAIT0()  asm volatile("cp.async.wait_group 0;" ::: "memory")
#define CPWAIT1()  asm volatile("cp.async.wait_group 1;" ::: "memory")

__device__ __forceinline__ void ldsm4(uint32_t addr, uint32_t* r) {
    asm volatile("ldmatrix.sync.aligned.m8n8.x4.shared.b16 {%0,%1,%2,%3}, [%4];"
        : "=r"(r[0]), "=r"(r[1]), "=r"(r[2]), "=r"(r[3]) : "r"(addr));
}
__device__ __forceinline__ void hmma(float* d, const uint32_t* a, const uint32_t* b) {
    asm volatile("mma.sync.aligned.m16n8k16.row.col.f32.f16.f16.f32 "
        "{%0,%1,%2,%3}, {%4,%5,%6,%7}, {%8,%9}, {%0,%1,%2,%3};"
        : "+f"(d[0]), "+f"(d[1]), "+f"(d[2]), "+f"(d[3])
        : "r"(a[0]), "r"(a[1]), "r"(a[2]), "r"(a[3]), "r"(b[0]), "r"(b[1]));
}
__device__ __forceinline__ float sigf(float x) {
    return __fdividef(1.0f, 1.0f + __expf(-x));
}
__device__ __forceinline__ float tanh_(float x) {
    float e = __expf(fminf(2.0f * x, 30.0f));
    return __fdividef(e - 1.0f, e + 1.0f);
}
__device__ __forceinline__ uint32_t packhl(float v0, float v1, int lo) {
    __half h0 = __float2half_rn(v0), h1 = __float2half_rn(v1);
    if (lo) {
        h0 = __float2half_rn(v0 - __half2float(h0));
        h1 = __float2half_rn(v1 - __half2float(h1));
    }
    return ((uint32_t)__half_as_ushort(h1) << 16) | __half_as_ushort(h0);
}

// ---------------- prep ----------------
__global__ void k_prep_emb(const float* __restrict__ emb) {
    int i = blockIdx.x * 256 + threadIdx.x;   // < 4096000
    float v = emb[i];
    __half h = __float2half_rn(v);
    g_eh[i] = h;
    g_el[i] = __float2half_rn(v - __half2float(h));
}
__global__ void k_prep_wif(const float* __restrict__ Wi_f, const float* __restrict__ Wi_b) {
    int i = blockIdx.x * 256 + threadIdx.x;   // < 131072
    int r = i & 1, lane = (i >> 1) & 31, nt = (i >> 6) & 7, ks = (i >> 9) & 7;
    int pt = (i >> 12) & 15, d = (i >> 16) & 1;
    int p = pt * 64 + nt * 8 + (lane >> 2), k0 = ks * 16 + r * 8 + (lane & 3) * 2;
    int col = (p & 3) * HID + (p >> 2);
    const float* W = d ? Wi_b : Wi_f;
    float v0 = W[(size_t)k0 * G4 + col], v1 = W[(size_t)(k0 + 1) * G4 + col];
    g_WiFh[i] = packhl(v0, v1, 0);
    g_WiFl[i] = packhl(v0, v1, 1);
}
__global__ void k_prep_whf(const float* __restrict__ Wh_f, const float* __restrict__ Wh_b) {
    int i = blockIdx.x * 256 + threadIdx.x;   // < 524288
    int r = i & 1, lane = (i >> 1) & 31, nt = (i >> 6) & 7, ks = (i >> 9) & 15;
    int jt = (i >> 13) & 15, d = (i >> 17) & 1;
    int p = jt * 64 + nt * 8 + (lane >> 2), k0 = ks * 16 + r * 8 + (lane & 3) * 2;
    int col = (p & 3) * HID + (p >> 2);
    const float* W = d ? Wh_b : Wh_f;
    float v0 = W[(size_t)k0 * G4 + col], v1 = W[(size_t)(k0 + 1) * G4 + col];
    g_WhFh[i] = packhl(v0, v1, 0);
}
__global__ void k_init() {
    int i = blockIdx.x * 256 + threadIdx.x;   // 65536 u32 = buffer 0 of g_hh
    ((uint32_t*)g_hh)[i] = 0u;
    if (i < 16) g_bar[i] = 0u;
}

// ---------------- xproj: eW = emb @ Wi (3-pass fp16 HMMA) + bias ----------------
#define XRS 272
__global__ void __launch_bounds__(256, 1)
k_xproj(const float* __restrict__ bf_, const float* __restrict__ bb_) {
    extern __shared__ __align__(16) char sm[];
    const uint32_t sb = smem_u32(sm);
    const int tid = threadIdx.x, lane = tid & 31, w = tid >> 5, wm = w >> 1, wn = w & 1;
    const int d = blockIdx.z, pt = blockIdx.y, v0 = blockIdx.x * 128;

    for (int i = tid; i < 128 * 16; i += 256) {
        int r = i >> 4, kb = (i & 15) * 16;
        CP16(sb + r * XRS + kb, (const char*)(g_eh + (size_t)(v0 + r) * 128) + kb);
        CP16(sb + 34816 + r * XRS + kb, (const char*)(g_el + (size_t)(v0 + r) * 128) + kb);
    }
    CPCOMMIT(); CPWAIT0();
    __syncthreads();

    float acc[32];
#pragma unroll
    for (int i = 0; i < 32; i++) acc[i] = 0.0f;
    const uint32_t aH = sb + (wm * 32 + (lane & 15)) * XRS + ((lane >> 4) * 8) * 2;
    const uint2* Bh = (const uint2*)g_WiFh + (d * 16 + pt) * 2048;
    const uint2* Bl = (const uint2*)g_WiFl + (d * 16 + pt) * 2048;

#pragma unroll
    for (int ks = 0; ks < 8; ks++) {
        uint32_t ah[8], al[8];
        ldsm4(aH + ks * 32, ah);
        ldsm4(aH + 16 * XRS + ks * 32, ah + 4);
        ldsm4(aH + 34816 + ks * 32, al);
        ldsm4(aH + 34816 + 16 * XRS + ks * 32, al + 4);
#pragma unroll
        for (int nt = 0; nt < 4; nt++) {
            int ntg = wn * 4 + nt;
            uint2 bh = __ldg(Bh + (ks * 8 + ntg) * 32 + lane);
            uint2 bl = __ldg(Bl + (ks * 8 + ntg) * 32 + lane);
#pragma unroll
            for (int mt = 0; mt < 2; mt++) {
                float* a = acc + (mt * 4 + nt) * 4;
                hmma(a, ah + mt * 4, (const uint32_t*)&bh);
                hmma(a, al + mt * 4, (const uint32_t*)&bh);
                hmma(a, ah + mt * 4, (const uint32_t*)&bl);
            }
        }
    }
    const float* bias = d ? bb_ : bf_;
#pragma unroll
    for (int mt = 0; mt < 2; mt++)
#pragma unroll
        for (int nt = 0; nt < 4; nt++) {
            int pc = pt * 64 + (wn * 4 + nt) * 8 + (lane & 3) * 2;
            float b0v = bias[(pc & 3) * HID + (pc >> 2)];
            float b1v = bias[((pc + 1) & 3) * HID + ((pc + 1) >> 2)];
            int v = v0 + wm * 32 + mt * 16 + (lane >> 2);
            float* a = acc + (mt * 4 + nt) * 4;
            *(float2*)(g_eW + ((size_t)d * VOC + v) * G4 + pc) = make_float2(a[0] + b0v, a[1] + b1v);
            *(float2*)(g_eW + ((size_t)d * VOC + v + 8) * G4 + pc) = make_float2(a[2] + b0v, a[3] + b1v);
        }
}

// ---------------- persistent recurrence: 128 CTAs x 512 thr, 8-CTA groups ----------------
// CTA: d = bi>>6, bq = (bi>>3)&7 (32 batch rows), jt = bi&7 (128 p-cols).
// 16 warps: wm = w>>3 (m16), wn = w&7 (n16). Wh fragments in registers.
// Per-warp self-contained epilogue+copy+arrive (no block sync before arrive).
#define LRS 528
#define HST 16896
#define LSZ 18944
__global__ void __launch_bounds__(512, 1)
k_lstm(const int* __restrict__ tokens) {
    extern __shared__ __align__(16) char sm[];
    const uint32_t sb = smem_u32(sm);
    const int tid = threadIdx.x, lane = tid & 31, w = tid >> 5, wm = w >> 3, wn = w & 7;
    const int bi = blockIdx.x, d = bi >> 6, bq = (bi >> 3) & 7, jt = bi & 7;
    const int b0 = bq * 32, grp = d * 8 + bq;

    // Wh fragments -> registers (step-invariant)
    uint2 brg[2][16];
#pragma unroll
    for (int nt = 0; nt < 2; nt++) {
        int ntg = wn * 2 + nt;
        const uint2* Bb = (const uint2*)g_WhFh + (size_t)(d * 16 + jt * 2 + (ntg >> 3)) * 4096;
#pragma unroll
        for (int ks = 0; ks < 16; ks++)
            brg[nt][ks] = __ldg(Bb + (ks * 8 + (ntg & 7)) * 32 + lane);
    }
    float cc[2] = {0.0f, 0.0f};
    const uint32_t aH = sb + (wm * 16 + (lane & 15)) * LRS + ((lane >> 4) * 8) * 2;
    const int r1 = wm * 16 + (lane >> 2);

    // tokens(0) -> xp(0) gather -> tokens(1)
    int sd0 = d ? (SS - 1) : 0;
    int tk0 = __ldg(tokens + (size_t)(b0 + r1) * SS + sd0);
    int tk1 = __ldg(tokens + (size_t)(b0 + r1 + 8) * SS + sd0);
    float xr[8];
#pragma unroll
    for (int nt = 0; nt < 2; nt++) {
        int pc = jt * 128 + (wn * 2 + nt) * 8 + (lane & 3) * 2;
        float2 x1 = *(const float2*)(g_eW + ((size_t)d * VOC + tk0) * G4 + pc);
        float2 x2 = *(const float2*)(g_eW + ((size_t)d * VOC + tk1) * G4 + pc);
        xr[nt * 4 + 0] = x1.x; xr[nt * 4 + 1] = x1.y;
        xr[nt * 4 + 2] = x2.x; xr[nt * 4 + 3] = x2.y;
    }
    int sd1 = d ? (SS - 2) : 1;
    tk0 = __ldg(tokens + (size_t)(b0 + r1) * SS + sd1);
    tk1 = __ldg(tokens + (size_t)(b0 + r1 + 8) * SS + sd1);
    __syncthreads();

    for (int s = 0; s < SS; s++) {
        const int cur = s & 1, nxt = cur ^ 1;

        // stage h tile (32 rows x 512B fp16) in two K-halves
        const char* hsh = (const char*)(g_hh + ((size_t)(cur * 2 + d) * BB + b0) * HID);
        {
            int i = tid;
            if (i < 512) {
                int r = i >> 4, kb = (i & 15) * 16;
                CP16(sb + r * LRS + kb, hsh + r * 512 + kb);
            }
        }
        CPCOMMIT();
        {
            int i = tid;
            if (i < 512) {
                int r = i >> 4, kb = 256 + (i & 15) * 16;
                CP16(sb + r * LRS + kb, hsh + r * 512 + kb);
            }
        }
        CPCOMMIT();

        float acc[8];
#pragma unroll
        for (int i = 0; i < 8; i++) acc[i] = xr[i];

        CPWAIT1();          // first K-half landed
        __syncthreads();

        // prefetch xp(s+1) (tk = tokens(s+1)), then tokens(s+2) — hidden under MMA
#pragma unroll
        for (int nt = 0; nt < 2; nt++) {
            int pc = jt * 128 + (wn * 2 + nt) * 8 + (lane & 3) * 2;
            float2 x1 = *(const float2*)(g_eW + ((size_t)d * VOC + tk0) * G4 + pc);
            float2 x2 = *(const float2*)(g_eW + ((size_t)d * VOC + tk1) * G4 + pc);
            xr[nt * 4 + 0] = x1.x; xr[nt * 4 + 1] = x1.y;
            xr[nt * 4 + 2] = x2.x; xr[nt * 4 + 3] = x2.y;
        }
        {
            int sn2 = (s + 2 < SS) ? s + 2 : 0;
            tk0 = __ldg(tokens + (size_t)(b0 + r1) * SS + (d ? (SS - 1 - sn2) : sn2));
            tk1 = __ldg(tokens + (size_t)(b0 + r1 + 8) * SS + (d ? (SS - 1 - sn2) : sn2));
        }

#pragma unroll
        for (int ks = 0; ks < 8; ks++) {
            uint32_t ah[4];
            ldsm4(aH + ks * 32, ah);
            hmma(acc + 0, ah, (const uint32_t*)&brg[0][ks]);
            hmma(acc + 4, ah, (const uint32_t*)&brg[1][ks]);
        }
        CPWAIT0();          // second K-half landed
        __syncthreads();
#pragma unroll
        for (int ks = 8; ks < 16; ks++) {
            uint32_t ah[4];
            ldsm4(aH + ks * 32, ah);
            hmma(acc + 0, ah, (const uint32_t*)&brg[0][ks]);
            hmma(acc + 4, ah, (const uint32_t*)&brg[1][ks]);
        }

        // epilogue -> smem h stage (fp16, 64B per row); warp-private region
#pragma unroll
        for (int nt = 0; nt < 2; nt++) {
            float* a = acc + nt * 4;
            float s0 = (lane & 1) ? a[0] : a[2];
            float s1 = (lane & 1) ? a[1] : a[3];
            float q0 = __shfl_xor_sync(0xFFFFFFFFu, s0, 1);
            float q1 = __shfl_xor_sync(0xFFFFFFFFu, s1, 1);
            float zi, zf, zg, zo;
            if (lane & 1) { zi = q0; zf = q1; zg = a[2]; zo = a[3]; }
            else          { zi = a[0]; zf = a[1]; zg = q0; zo = q1; }
            float ii = sigf(zi), ff = sigf(zf), gg = tanh_(zg), oo = sigf(zo);
            cc[nt] = ff * cc[nt] + ii * gg;
            float h = oo * tanh_(cc[nt]);
            int row = wm * 16 + (lane >> 2) + ((lane & 1) ? 8 : 0);
            int jloc = (wn * 2 + nt) * 2 + ((lane & 2) ? 1 : 0);
            *(__half*)(sm + HST + row * 64 + jloc * 2) = __float2half_rn(h);
        }
        __syncwarp();

        // per-warp copy of OWN region (16 rows x 8B) -> global, then arrive
        {
            int r = wm * 16 + (lane >> 1), q = lane & 1;
            uint32_t v = *(const uint32_t*)(sm + HST + r * 64 + wn * 8 + q * 4);
            char* dstb = (char*)g_hh + ((size_t)(nxt * 2 + d) * BB) * HID * 2;
            *(uint32_t*)(dstb + (size_t)(b0 + r) * 512 + jt * 64 + wn * 8 + q * 4) = v;
        }
        __syncwarp();
        if (lane == 0)
            asm volatile("red.release.gpu.add.u32 [%0], 1;" :: "l"(g_bar + grp) : "memory");

        if (tid == 0) {
            const unsigned tgt = 128u * (unsigned)(s + 1);
            unsigned v;
            do {
                asm volatile("ld.acquire.gpu.b32 %0, [%1];" : "=r"(v) : "l"(g_bar + grp) : "memory");
            } while (v < tgt);
        }
        __syncthreads();
    }
#pragma unroll
    for (int nt = 0; nt < 2; nt++) {
        int row = wm * 16 + (lane >> 2) + ((lane & 1) ? 8 : 0);
        int j = jt * 32 + (wn * 2 + nt) * 2 + ((lane & 2) ? 1 : 0);
        g_c[((size_t)d * BB + b0 + row) * HID + j] = cc[nt];
    }
}

// ---------------- classifier ----------------
__global__ void k_cls(const float* __restrict__ Wd, const float* __restrict__ bd,
                      float* __restrict__ out) {
    const int b = blockIdx.x, t = threadIdx.x;
    float cf = g_c[(size_t)(0 * BB + b) * HID + t];
    float cb = g_c[(size_t)(1 * BB + b) * HID + t];
    float p[8];
#pragma unroll
    for (int n = 0; n < 8; n++)
        p[n] = cf * Wd[t * NCLS + n] + cb * Wd[(HID + t) * NCLS + n];
#pragma unroll
    for (int n = 0; n < 8; n++)
#pragma unroll
        for (int off = 16; off > 0; off >>= 1)
            p[n] += __shfl_down_sync(0xFFFFFFFFu, p[n], off);
    __shared__ float smc[8][8];
    const int wi = t >> 5, lane = t & 31;
    if (lane == 0) {
#pragma unroll
        for (int n = 0; n < 8; n++) smc[wi][n] = p[n];
    }
    __syncthreads();
    if (t < NCLS) {
        float a = bd[t];
#pragma unroll
        for (int ww = 0; ww < 8; ww++) a += smc[ww][t];
        out[b * NCLS + t] = a;
    }
}

// ---------------- launch ----------------
extern "C" void kernel_launch(void* const* d_in, const int* in_sizes, int n_in,
                              void* d_out, int out_size) {
    const int*   tokens = (const int*)  d_in[0];
    const float* emb    = (const float*)d_in[1];
    const float* Wi_f   = (const float*)d_in[2];
    const float* Wh_f   = (const float*)d_in[3];
    const float* b_f    = (const float*)d_in[4];
    const float* Wi_b   = (const float*)d_in[5];
    const float* Wh_b   = (const float*)d_in[6];
    const float* b_b    = (const float*)d_in[7];
    const float* Wd     = (const float*)d_in[8];
    const float* bd     = (const float*)d_in[9];
    float*       out    = (float*)d_out;
    (void)in_sizes; (void)n_in; (void)out_size;

    static bool done = false;
    if (!done) {
        cudaFuncSetAttribute(k_xproj, cudaFuncAttributeMaxDynamicSharedMemorySize, 69632);
        cudaFuncSetAttribute(k_lstm,  cudaFuncAttributeMaxDynamicSharedMemorySize, LSZ);
        done = true;
    }
    k_prep_emb<<<16000, 256>>>(emb);
    k_prep_wif<<<512, 256>>>(Wi_f, Wi_b);
    k_prep_whf<<<2048, 256>>>(Wh_f, Wh_b);
    k_init<<<256, 256>>>();
    k_xproj<<<dim3(250, 16, 2), 256, 69632>>>(b_f, b_b);
    k_lstm<<<128, 512, LSZ>>>(tokens);
    k_cls<<<256, 256>>>(Wd, bd, out);
}

// round 17
// speedup vs baseline: 1.1134x; 1.1134x over previous
#include <cuda_runtime.h>
#include <cuda_fp16.h>
#include <stdint.h>

#define SS 512
#define BB 256
#define VOC 32000
#define HID 256
#define G4 1024
#define NCLS 8

__device__ float g_eW[(size_t)2 * VOC * G4];                 // [d][v][p], bias baked
__device__ __align__(16) __half g_eh[VOC * 128], g_el[VOC * 128];
__device__ __align__(16) uint32_t g_WiFh[131072], g_WiFl[131072];
__device__ __align__(16) uint32_t g_WhFh[524288];
__device__ __align__(16) __half g_hh[2 * 2 * BB * HID];      // ping-pong h (fp16)
__device__ float g_c[2 * BB * HID];
__device__ __align__(128) unsigned g_bar[8 * 32];            // one counter per 128B line

__device__ __forceinline__ uint32_t smem_u32(const void* p) {
    uint32_t a;
    asm("{ .reg .u64 t; cvta.to.shared.u64 t, %1; cvt.u32.u64 %0, t; }" : "=r"(a) : "l"(p));
    return a;
}
#define CP16(dst, src) asm volatile("cp.async.cg.shared.global [%0], [%1], 16;" :: "r"(dst), "l"(src))
#define CPCOMMIT() asm volatile("cp.async.commit_group;" ::: "memory")
#define CPWAIT0()  asm volatile("cp.async.wait_group 0;" ::: "memory")
#define CPWAIT1()  asm volatile("cp.async.wait_group 1;" ::: "memory")

__device__ __forceinline__ void ldsm4(uint32_t addr, uint32_t* r) {
    asm volatile("ldmatrix.sync.aligned.m8n8.x4.shared.b16 {%0,%1,%2,%3}, [%4];"
        : "=r"(r[0]), "=r"(r[1]), "=r"(r[2]), "=r"(r[3]) : "r"(addr));
}
__device__ __forceinline__ void hmma(float* d, const uint32_t* a, const uint32_t* b) {
    asm volatile("mma.sync.aligned.m16n8k16.row.col.f32.f16.f16.f32 "
        "{%0,%1,%2,%3}, {%4,%5,%6,%7}, {%8,%9}, {%0,%1,%2,%3};"
        : "+f"(d[0]), "+f"(d[1]), "+f"(d[2]), "+f"(d[3])
        : "r"(a[0]), "r"(a[1]), "r"(a[2]), "r"(a[3]), "r"(b[0]), "r"(b[1]));
}
__device__ __forceinline__ float sigf(float x) {
    return __fdividef(1.0f, 1.0f + __expf(-x));
}
__device__ __forceinline__ float tanh_(float x) {
    float e = __expf(fminf(2.0f * x, 30.0f));
    return __fdividef(e - 1.0f, e + 1.0f);
}
__device__ __forceinline__ uint32_t packhl(float v0, float v1, int lo) {
    __half h0 = __float2half_rn(v0), h1 = __float2half_rn(v1);
    if (lo) {
        h0 = __float2half_rn(v0 - __half2float(h0));
        h1 = __float2half_rn(v1 - __half2float(h1));
    }
    return ((uint32_t)__half_as_ushort(h1) << 16) | __half_as_ushort(h0);
}

// ---------------- prep ----------------
__global__ void k_prep_emb(const float* __restrict__ emb) {
    int i = blockIdx.x * 256 + threadIdx.x;   // < 4096000
    float v = emb[i];
    __half h = __float2half_rn(v);
    g_eh[i] = h;
    g_el[i] = __float2half_rn(v - __half2float(h));
}
__global__ void k_prep_wif(const float* __restrict__ Wi_f, const float* __restrict__ Wi_b) {
    int i = blockIdx.x * 256 + threadIdx.x;   // < 131072
    int r = i & 1, lane = (i >> 1) & 31, nt = (i >> 6) & 7, ks = (i >> 9) & 7;
    int pt = (i >> 12) & 15, d = (i >> 16) & 1;
    int p = pt * 64 + nt * 8 + (lane >> 2), k0 = ks * 16 + r * 8 + (lane & 3) * 2;
    int col = (p & 3) * HID + (p >> 2);
    const float* W = d ? Wi_b : Wi_f;
    float v0 = W[(size_t)k0 * G4 + col], v1 = W[(size_t)(k0 + 1) * G4 + col];
    g_WiFh[i] = packhl(v0, v1, 0);
    g_WiFl[i] = packhl(v0, v1, 1);
}
__global__ void k_prep_whf(const float* __restrict__ Wh_f, const float* __restrict__ Wh_b) {
    int i = blockIdx.x * 256 + threadIdx.x;   // < 524288
    int r = i & 1, lane = (i >> 1) & 31, nt = (i >> 6) & 7, ks = (i >> 9) & 15;
    int jt = (i >> 13) & 15, d = (i >> 17) & 1;
    int p = jt * 64 + nt * 8 + (lane >> 2), k0 = ks * 16 + r * 8 + (lane & 3) * 2;
    int col = (p & 3) * HID + (p >> 2);
    const float* W = d ? Wh_b : Wh_f;
    float v0 = W[(size_t)k0 * G4 + col], v1 = W[(size_t)(k0 + 1) * G4 + col];
    g_WhFh[i] = packhl(v0, v1, 0);
}
__global__ void k_init() {
    int i = blockIdx.x * 256 + threadIdx.x;   // 65536 u32 = buffer 0 of g_hh
    ((uint32_t*)g_hh)[i] = 0u;
    if (i < 8 * 32) g_bar[i] = 0u;
}

// ---------------- xproj: eW = emb @ Wi (3-pass fp16 HMMA) + bias ----------------
#define XRS 272
__global__ void __launch_bounds__(256, 1)
k_xproj(const float* __restrict__ bf_, const float* __restrict__ bb_) {
    extern __shared__ __align__(16) char sm[];
    const uint32_t sb = smem_u32(sm);
    const int tid = threadIdx.x, lane = tid & 31, w = tid >> 5, wm = w >> 1, wn = w & 1;
    const int d = blockIdx.z, pt = blockIdx.y, v0 = blockIdx.x * 128;

    for (int i = tid; i < 128 * 16; i += 256) {
        int r = i >> 4, kb = (i & 15) * 16;
        CP16(sb + r * XRS + kb, (const char*)(g_eh + (size_t)(v0 + r) * 128) + kb);
        CP16(sb + 34816 + r * XRS + kb, (const char*)(g_el + (size_t)(v0 + r) * 128) + kb);
    }
    CPCOMMIT(); CPWAIT0();
    __syncthreads();

    float acc[32];
#pragma unroll
    for (int i = 0; i < 32; i++) acc[i] = 0.0f;
    const uint32_t aH = sb + (wm * 32 + (lane & 15)) * XRS + ((lane >> 4) * 8) * 2;
    const uint2* Bh = (const uint2*)g_WiFh + (d * 16 + pt) * 2048;
    const uint2* Bl = (const uint2*)g_WiFl + (d * 16 + pt) * 2048;

#pragma unroll
    for (int ks = 0; ks < 8; ks++) {
        uint32_t ah[8], al[8];
        ldsm4(aH + ks * 32, ah);
        ldsm4(aH + 16 * XRS + ks * 32, ah + 4);
        ldsm4(aH + 34816 + ks * 32, al);
        ldsm4(aH + 34816 + 16 * XRS + ks * 32, al + 4);
#pragma unroll
        for (int nt = 0; nt < 4; nt++) {
            int ntg = wn * 4 + nt;
            uint2 bh = __ldg(Bh + (ks * 8 + ntg) * 32 + lane);
            uint2 bl = __ldg(Bl + (ks * 8 + ntg) * 32 + lane);
#pragma unroll
            for (int mt = 0; mt < 2; mt++) {
                float* a = acc + (mt * 4 + nt) * 4;
                hmma(a, ah + mt * 4, (const uint32_t*)&bh);
                hmma(a, al + mt * 4, (const uint32_t*)&bh);
                hmma(a, ah + mt * 4, (const uint32_t*)&bl);
            }
        }
    }
    const float* bias = d ? bb_ : bf_;
#pragma unroll
    for (int mt = 0; mt < 2; mt++)
#pragma unroll
        for (int nt = 0; nt < 4; nt++) {
            int pc = pt * 64 + (wn * 4 + nt) * 8 + (lane & 3) * 2;
            float b0v = bias[(pc & 3) * HID + (pc >> 2)];
            float b1v = bias[((pc + 1) & 3) * HID + ((pc + 1) >> 2)];
            int v = v0 + wm * 32 + mt * 16 + (lane >> 2);
            float* a = acc + (mt * 4 + nt) * 4;
            *(float2*)(g_eW + ((size_t)d * VOC + v) * G4 + pc) = make_float2(a[0] + b0v, a[1] + b1v);
            *(float2*)(g_eW + ((size_t)d * VOC + v + 8) * G4 + pc) = make_float2(a[2] + b0v, a[3] + b1v);
        }
}

// ---------------- persistent recurrence: 128 CTAs x 512 thr ----------------
// CTA: d = bi>>6, bq = (bi>>4)&3 (batch quarter, 64 rows), jt = bi&15.
// 16 warps: wm = w>>2 (m16 tile), wn = w&3 (n16). Wh fragments in REGISTERS.
// Padded per-group counters (one per 128B line); per-warp arrive+poll.
#define LRS 528
#define HST 33792
#define LSZ 35840
__global__ void __launch_bounds__(512, 1)
k_lstm(const int* __restrict__ tokens) {
    extern __shared__ __align__(16) char sm[];
    const uint32_t sb = smem_u32(sm);
    const int tid = threadIdx.x, lane = tid & 31, w = tid >> 5, wm = w >> 2, wn = w & 3;
    const int bi = blockIdx.x, d = bi >> 6, bq = (bi >> 4) & 3, jt = bi & 15;
    const int b0 = bq * 64;
    unsigned* barp = g_bar + (d * 4 + bq) * 32;

    // Wh fragments -> registers (step-invariant, held for all 512 steps)
    const uint2* Bh = (const uint2*)g_WhFh + (size_t)(d * 16 + jt) * 4096;
    uint2 brg[2][16];
#pragma unroll
    for (int ks = 0; ks < 16; ks++) {
        brg[0][ks] = __ldg(Bh + (ks * 8 + wn * 2 + 0) * 32 + lane);
        brg[1][ks] = __ldg(Bh + (ks * 8 + wn * 2 + 1) * 32 + lane);
    }
    float cc[2] = {0.0f, 0.0f};
    const uint32_t aH = sb + (wm * 16 + (lane & 15)) * LRS + ((lane >> 4) * 8) * 2;
    const int r1 = wm * 16 + (lane >> 2);

    // tokens(0) -> xp(0) gather -> tokens(1)
    int sd0 = d ? (SS - 1) : 0;
    int tk0 = __ldg(tokens + (size_t)(b0 + r1) * SS + sd0);
    int tk1 = __ldg(tokens + (size_t)(b0 + r1 + 8) * SS + sd0);
    float xr[8];
#pragma unroll
    for (int nt = 0; nt < 2; nt++) {
        int pc = jt * 64 + (wn * 2 + nt) * 8 + (lane & 3) * 2;
        float2 x1 = *(const float2*)(g_eW + ((size_t)d * VOC + tk0) * G4 + pc);
        float2 x2 = *(const float2*)(g_eW + ((size_t)d * VOC + tk1) * G4 + pc);
        xr[nt * 4 + 0] = x1.x; xr[nt * 4 + 1] = x1.y;
        xr[nt * 4 + 2] = x2.x; xr[nt * 4 + 3] = x2.y;
    }
    int sd1 = d ? (SS - 2) : 1;
    tk0 = __ldg(tokens + (size_t)(b0 + r1) * SS + sd1);
    tk1 = __ldg(tokens + (size_t)(b0 + r1 + 8) * SS + sd1);
    __syncthreads();

    for (int s = 0; s < SS; s++) {
        const int cur = s & 1, nxt = cur ^ 1;

        // stage h tile (64 rows x 512B fp16) in two K-halves (1024 CP16s each)
        const char* hsh = (const char*)(g_hh + ((size_t)(cur * 2 + d) * BB + b0) * HID);
        for (int i = tid; i < 1024; i += 512) {
            int r = i >> 4, kb = (i & 15) * 16;
            CP16(sb + r * LRS + kb, hsh + r * 512 + kb);
        }
        CPCOMMIT();
        for (int i = tid; i < 1024; i += 512) {
            int r = i >> 4, kb = 256 + (i & 15) * 16;
            CP16(sb + r * LRS + kb, hsh + r * 512 + kb);
        }
        CPCOMMIT();

        float acc[8];
#pragma unroll
        for (int i = 0; i < 8; i++) acc[i] = xr[i];

        CPWAIT1();          // first K-half landed
        __syncthreads();    // all stages visible; all copies of step s-1 done

        // prefetch xp(s+1) (tk = tokens(s+1)), then tokens(s+2) — hidden under MMA
#pragma unroll
        for (int nt = 0; nt < 2; nt++) {
            int pc = jt * 64 + (wn * 2 + nt) * 8 + (lane & 3) * 2;
            float2 x1 = *(const float2*)(g_eW + ((size_t)d * VOC + tk0) * G4 + pc);
            float2 x2 = *(const float2*)(g_eW + ((size_t)d * VOC + tk1) * G4 + pc);
            xr[nt * 4 + 0] = x1.x; xr[nt * 4 + 1] = x1.y;
            xr[nt * 4 + 2] = x2.x; xr[nt * 4 + 3] = x2.y;
        }
        {
            int sn2 = (s + 2 < SS) ? s + 2 : 0;
            tk0 = __ldg(tokens + (size_t)(b0 + r1) * SS + (d ? (SS - 1 - sn2) : sn2));
            tk1 = __ldg(tokens + (size_t)(b0 + r1 + 8) * SS + (d ? (SS - 1 - sn2) : sn2));
        }

#pragma unroll
        for (int ks = 0; ks < 8; ks++) {
            uint32_t ah[4];
            ldsm4(aH + ks * 32, ah);
            hmma(acc + 0, ah, (const uint32_t*)&brg[0][ks]);
            hmma(acc + 4, ah, (const uint32_t*)&brg[1][ks]);
        }
        CPWAIT0();          // second K-half landed
        __syncthreads();
#pragma unroll
        for (int ks = 8; ks < 16; ks++) {
            uint32_t ah[4];
            ldsm4(aH + ks * 32, ah);
            hmma(acc + 0, ah, (const uint32_t*)&brg[0][ks]);
            hmma(acc + 4, ah, (const uint32_t*)&brg[1][ks]);
        }

        // epilogue -> smem h stage (fp16, 32B per row)
#pragma unroll
        for (int nt = 0; nt < 2; nt++) {
            float* a = acc + nt * 4;
            float s0 = (lane & 1) ? a[0] : a[2];
            float s1 = (lane & 1) ? a[1] : a[3];
            float q0 = __shfl_xor_sync(0xFFFFFFFFu, s0, 1);
            float q1 = __shfl_xor_sync(0xFFFFFFFFu, s1, 1);
            float zi, zf, zg, zo;
            if (lane & 1) { zi = q0; zf = q1; zg = a[2]; zo = a[3]; }
            else          { zi = a[0]; zf = a[1]; zg = q0; zo = q1; }
            float ii = sigf(zi), ff = sigf(zf), gg = tanh_(zg), oo = sigf(zo);
            cc[nt] = ff * cc[nt] + ii * gg;
            float h = oo * tanh_(cc[nt]);
            int row = wm * 16 + (lane >> 2) + ((lane & 1) ? 8 : 0);
            int jloc = (wn * 2 + nt) * 2 + ((lane & 2) ? 1 : 0);
            *(__half*)(sm + HST + row * 32 + jloc * 2) = __float2half_rn(h);
        }
        __syncthreads();    // all ldsm done CTA-wide AND h stage complete

        // coalesced copy h stage -> global (4B per thread)
        {
            int r = tid >> 3, q = tid & 7;
            uint32_t v = *(const uint32_t*)(sm + HST + r * 32 + q * 4);
            char* dstb = (char*)g_hh + ((size_t)(nxt * 2 + d) * BB) * HID * 2;
            *(uint32_t*)(dstb + (size_t)(b0 + r) * 512 + jt * 32 + q * 4) = v;
        }
        __syncwarp();
        // per-warp arrive + poll (no block sync after; top-of-loop sync covers it)
        if (lane == 0) {
            asm volatile("red.release.gpu.add.u32 [%0], 1;" :: "l"(barp) : "memory");
            const unsigned tgt = 256u * (unsigned)(s + 1);
            unsigned v;
            do {
                asm volatile("ld.acquire.gpu.b32 %0, [%1];" : "=r"(v) : "l"(barp) : "memory");
            } while (v < tgt);
        }
        __syncwarp();
    }
#pragma unroll
    for (int nt = 0; nt < 2; nt++) {
        int row = wm * 16 + (lane >> 2) + ((lane & 1) ? 8 : 0);
        int j = jt * 16 + (wn * 2 + nt) * 2 + ((lane & 2) ? 1 : 0);
        g_c[((size_t)d * BB + b0 + row) * HID + j] = cc[nt];
    }
}

// ---------------- classifier ----------------
__global__ void k_cls(const float* __restrict__ Wd, const float* __restrict__ bd,
                      float* __restrict__ out) {
    const int b = blockIdx.x, t = threadIdx.x;
    float cf = g_c[(size_t)(0 * BB + b) * HID + t];
    float cb = g_c[(size_t)(1 * BB + b) * HID + t];
    float p[8];
#pragma unroll
    for (int n = 0; n < 8; n++)
        p[n] = cf * Wd[t * NCLS + n] + cb * Wd[(HID + t) * NCLS + n];
#pragma unroll
    for (int n = 0; n < 8; n++)
#pragma unroll
        for (int off = 16; off > 0; off >>= 1)
            p[n] += __shfl_down_sync(0xFFFFFFFFu, p[n], off);
    __shared__ float smc[8][8];
    const int wi = t >> 5, lane = t & 31;
    if (lane == 0) {
#pragma unroll
        for (int n = 0; n < 8; n++) smc[wi][n] = p[n];
    }
    __syncthreads();
    if (t < NCLS) {
        float a = bd[t];
#pragma unroll
        for (int ww = 0; ww < 8; ww++) a += smc[ww][t];
        out[b * NCLS + t] = a;
    }
}

// ---------------- launch ----------------
extern "C" void kernel_launch(void* const* d_in, const int* in_sizes, int n_in,
                              void* d_out, int out_size) {
    const int*   tokens = (const int*)  d_in[0];
    const float* emb    = (const float*)d_in[1];
    const float* Wi_f   = (const float*)d_in[2];
    const float* Wh_f   = (const float*)d_in[3];
    const float* b_f    = (const float*)d_in[4];
    const float* Wi_b   = (const float*)d_in[5];
    const float* Wh_b   = (const float*)d_in[6];
    const float* b_b    = (const float*)d_in[7];
    const float* Wd     = (const float*)d_in[8];
    const float* bd     = (const float*)d_in[9];
    float*       out    = (float*)d_out;
    (void)in_sizes; (void)n_in; (void)out_size;

    static bool done = false;
    if (!done) {
        cudaFuncSetAttribute(k_xproj, cudaFuncAttributeMaxDynamicSharedMemorySize, 69632);
        cudaFuncSetAttribute(k_lstm,  cudaFuncAttributeMaxDynamicSharedMemorySize, LSZ);
        done = true;
    }
    k_prep_emb<<<16000, 256>>>(emb);
    k_prep_wif<<<512, 256>>>(Wi_f, Wi_b);
    k_prep_whf<<<2048, 256>>>(Wh_f, Wh_b);
    k_init<<<256, 256>>>();
    k_xproj<<<dim3(250, 16, 2), 256, 69632>>>(b_f, b_b);
    k_lstm<<<128, 512, LSZ>>>(tokens);
    k_cls<<<256, 256>>>(Wd, bd, out);
}